// round 13
// baseline (speedup 1.0000x reference)
#include <cuda_runtime.h>
#include <cuda_fp16.h>
#include <cstdint>

#define BB 256
#define SS 512
#define N_IN 2048
#define N_OUT 512
#define HH 30
#define ROWS (BB*SS)   // 131072

// ---------------- device scratch ----------------
__device__ float g_flat[(size_t)ROWS * HH];
__device__ float g_partial[1024 * 64];
__device__ float g_mu[HH];
__device__ float g_rstd[HH];
// pre-converted fp16 weights, transposed [n][k]
__device__ __half g_w1h[32 * N_IN];      // 128 KB
__device__ __half g_woh[N_OUT * 32];     // 32 KB

// ---------------- helpers ----------------
__device__ __forceinline__ void mma_f16(float& c0, float& c1, float& c2, float& c3,
                                        uint32_t a0, uint32_t a1, uint32_t a2, uint32_t a3,
                                        uint32_t b0, uint32_t b1) {
    asm volatile(
        "mma.sync.aligned.m16n8k16.row.col.f32.f16.f16.f32 "
        "{%0,%1,%2,%3},{%4,%5,%6,%7},{%8,%9},{%0,%1,%2,%3};"
        : "+f"(c0), "+f"(c1), "+f"(c2), "+f"(c3)
        : "r"(a0), "r"(a1), "r"(a2), "r"(a3), "r"(b0), "r"(b1));
}
__device__ __forceinline__ float htanh(float x) {
    float r; asm("tanh.approx.f32 %0,%1;" : "=f"(r) : "f"(x)); return r;
}
__device__ __forceinline__ float hsig(float x) {
    return fmaf(htanh(x * 0.5f), 0.5f, 0.5f);
}
__device__ __forceinline__ uint32_t h2u(__half2 h) {
    return *reinterpret_cast<uint32_t*>(&h);
}

// ---------------- prep: W1/Wout -> fp16, transposed [n][k] ----------
__global__ __launch_bounds__(256)
void prep_w_kernel(const float* __restrict__ W1, const float* __restrict__ Wout)
{
    int i = blockIdx.x * 256 + threadIdx.x;
    if (i < 32 * N_IN) {
        int k = i >> 5, n = i & 31;
        float w = (n < HH) ? W1[(size_t)k * HH + n] : 0.f;
        g_w1h[n * N_IN + k] = __float2half_rn(w);
    }
    int j = i - 32 * N_IN;
    if (j >= 0 && j < N_OUT * 32) {
        int n = j >> 5, k = j & 31;
        float w = (k < HH) ? Wout[(size_t)k * N_OUT + n] : 0.f;
        g_woh[n * 32 + k] = __float2half_rn(w);
    }
}

// ================= fc1: fp16 mma m16n8k16, double-buffered ====================
// C[131072,30] = X @ W1; +bias, ReLU, BN partials.
__global__ __launch_bounds__(256)
void fc1_mma_kernel(const float* __restrict__ x, const float* __restrict__ b1)
{
    __shared__ __align__(16) __half a_s[2][128][40];   // 20.5 KB
    __shared__ __align__(16) __half b_s[2][32][40];    // 5.1 KB
    __shared__ float bias_s[32];
    __shared__ float red[2][256];

    const int tid  = threadIdx.x;
    const int wid  = tid >> 5;
    const int lane = tid & 31;
    const int g    = lane >> 2;
    const int tg   = lane & 3;
    const size_t rowBase = (size_t)blockIdx.x * 128;

    if (tid < 32) bias_s[tid] = (tid < HH) ? b1[tid] : 0.f;

    float c[4][4];
    #pragma unroll
    for (int nt = 0; nt < 4; nt++)
        #pragma unroll
        for (int q = 0; q < 4; q++) c[nt][q] = 0.f;

    const int ar = tid >> 1;             // A row 0..127 (2 threads/row)
    const int kb = (tid & 1) * 16;       // k base: 0 or 16
    const int bn = tid >> 3;             // B: n 0..31
    const int bf = tid & 7;              // B: 4-halfs idx 0..7
    float4 pfa4[4];
    uint2  pfb;

    auto prefetch = [&](int j) {
        const float* xp = &x[(rowBase + ar) * (size_t)N_IN + j * 32 + kb];
        #pragma unroll
        for (int q = 0; q < 4; q++) pfa4[q] = *(const float4*)(xp + q * 4);
        const uint2* wb = (const uint2*)g_w1h;       // 4 halfs per uint2; 512 per n
        pfb = wb[(size_t)bn * (N_IN / 4) + j * 8 + bf];
    };
    auto store_stage = [&](int st) {
        __half2 h[8];
        h[0] = __float22half2_rn(make_float2(pfa4[0].x, pfa4[0].y));
        h[1] = __float22half2_rn(make_float2(pfa4[0].z, pfa4[0].w));
        h[2] = __float22half2_rn(make_float2(pfa4[1].x, pfa4[1].y));
        h[3] = __float22half2_rn(make_float2(pfa4[1].z, pfa4[1].w));
        h[4] = __float22half2_rn(make_float2(pfa4[2].x, pfa4[2].y));
        h[5] = __float22half2_rn(make_float2(pfa4[2].z, pfa4[2].w));
        h[6] = __float22half2_rn(make_float2(pfa4[3].x, pfa4[3].y));
        h[7] = __float22half2_rn(make_float2(pfa4[3].z, pfa4[3].w));
        uint4* dst = (uint4*)&a_s[st][ar][kb];
        dst[0] = make_uint4(h2u(h[0]), h2u(h[1]), h2u(h[2]), h2u(h[3]));
        dst[1] = make_uint4(h2u(h[4]), h2u(h[5]), h2u(h[6]), h2u(h[7]));
        *(uint2*)&b_s[st][bn][bf * 4] = pfb;
    };

    prefetch(0);
    store_stage(0);
    __syncthreads();
    prefetch(1);

    const int mr = wid * 16;
    for (int j = 0; j < 64; j++) {
        const int cur = j & 1, nxt = cur ^ 1;
        if (j < 63) store_stage(nxt);
        if (j < 62) prefetch(j + 2);
        #pragma unroll
        for (int ks = 0; ks < 2; ks++) {
            const int k0 = ks * 16;
            uint32_t a0 = *(const uint32_t*)&a_s[cur][mr + g    ][k0 + 2*tg    ];
            uint32_t a1 = *(const uint32_t*)&a_s[cur][mr + g + 8][k0 + 2*tg    ];
            uint32_t a2 = *(const uint32_t*)&a_s[cur][mr + g    ][k0 + 2*tg + 8];
            uint32_t a3 = *(const uint32_t*)&a_s[cur][mr + g + 8][k0 + 2*tg + 8];
            #pragma unroll
            for (int nt = 0; nt < 4; nt++) {
                uint32_t b0 = *(const uint32_t*)&b_s[cur][nt*8 + g][k0 + 2*tg    ];
                uint32_t b1 = *(const uint32_t*)&b_s[cur][nt*8 + g][k0 + 2*tg + 8];
                mma_f16(c[nt][0], c[nt][1], c[nt][2], c[nt][3], a0, a1, a2, a3, b0, b1);
            }
        }
        __syncthreads();
    }

    // epilogue: bias + ReLU + store + BN partials
    size_t r0 = rowBase + wid * 16 + g;
    size_t r1 = r0 + 8;
    #pragma unroll
    for (int nt = 0; nt < 4; nt++) {
        int col = nt * 8 + tg * 2;
        float v00 = 0.f, v01 = 0.f, v10 = 0.f, v11 = 0.f;
        if (col < HH) {
            v00 = fmaxf(c[nt][0] + bias_s[col],     0.f);
            v01 = fmaxf(c[nt][1] + bias_s[col + 1], 0.f);
            v10 = fmaxf(c[nt][2] + bias_s[col],     0.f);
            v11 = fmaxf(c[nt][3] + bias_s[col + 1], 0.f);
            *(float2*)&g_flat[r0 * HH + col] = make_float2(v00, v01);
            *(float2*)&g_flat[r1 * HH + col] = make_float2(v10, v11);
        }
        float s0 = v00 + v10, q0 = v00 * v00 + v10 * v10;
        float s1 = v01 + v11, q1 = v01 * v01 + v11 * v11;
        #pragma unroll
        for (int off = 4; off < 32; off <<= 1) {
            s0 += __shfl_xor_sync(0xffffffffu, s0, off);
            q0 += __shfl_xor_sync(0xffffffffu, q0, off);
            s1 += __shfl_xor_sync(0xffffffffu, s1, off);
            q1 += __shfl_xor_sync(0xffffffffu, q1, off);
        }
        if (g == 0) {
            red[0][(col    ) * 8 + wid] = s0;
            red[0][(col + 1) * 8 + wid] = s1;
            red[1][(col    ) * 8 + wid] = q0;
            red[1][(col + 1) * 8 + wid] = q1;
        }
    }
    __syncthreads();
    if (tid < HH) {
        float s = 0.f, q = 0.f;
        #pragma unroll
        for (int w = 0; w < 8; w++) { s += red[0][tid * 8 + w]; q += red[1][tid * 8 + w]; }
        g_partial[blockIdx.x * 60 + tid]      = s;
        g_partial[blockIdx.x * 60 + 30 + tid] = q;
    }
}

// ---------------- BN finalize ----------------
__global__ void bn_stats_kernel()
{
    __shared__ float rs[2][HH][9];
    int c = threadIdx.x & 31;
    int g = threadIdx.x >> 5;
    if (c < HH) {
        float s = 0.f, q = 0.f;
        for (int p = g; p < 1024; p += 8) {
            s += g_partial[p * 60 + c];
            q += g_partial[p * 60 + 30 + c];
        }
        rs[0][c][g] = s; rs[1][c][g] = q;
    }
    __syncthreads();
    if (threadIdx.x < HH) {
        float s = 0.f, q = 0.f;
        #pragma unroll
        for (int g2 = 0; g2 < 8; g2++) { s += rs[0][threadIdx.x][g2]; q += rs[1][threadIdx.x][g2]; }
        const float n = (float)ROWS;
        float mu  = s / n;
        float var = q / n - mu * mu;
        g_mu[threadIdx.x]   = mu;
        g_rstd[threadIdx.x] = rsqrtf(var + 1e-5f);
    }
}

// ---------------- LSTM (R6-proven: scalar dots + MUFU tanh) ----------------
#define LSTM_THREADS 256
#define LSTM_SMEM_FLOATS (SS*32 + 32 + 32 + 32 + 128 + 128 + 32 + 32)
#define LSTM_SMEM_BYTES  (LSTM_SMEM_FLOATS * 4)

__device__ __forceinline__ float dot_step(const float* __restrict__ xv,
                                          const float* __restrict__ hv,
                                          const float (&wi)[32], const float (&wh)[32],
                                          float bj)
{
    const float4* x4 = (const float4*)xv;
    const float4* h4 = (const float4*)hv;
    float a0 = bj, a1 = 0.f, a2 = 0.f, a3 = 0.f;
    float b0 = 0.f, b1 = 0.f, b2 = 0.f, b3 = 0.f;
    #pragma unroll
    for (int q = 0; q < 8; q++) {
        float4 xq = x4[q];
        a0 += wi[4*q+0] * xq.x; a1 += wi[4*q+1] * xq.y;
        a2 += wi[4*q+2] * xq.z; a3 += wi[4*q+3] * xq.w;
        float4 hq = h4[q];
        b0 += wh[4*q+0] * hq.x; b1 += wh[4*q+1] * hq.y;
        b2 += wh[4*q+2] * hq.z; b3 += wh[4*q+3] * hq.w;
    }
    return ((a0 + a1) + (a2 + a3)) + ((b0 + b1) + (b2 + b3));
}

__global__ __launch_bounds__(LSTM_THREADS, 2)
void lstm_kernel(const float* __restrict__ h0, const float* __restrict__ c0,
                 const float* __restrict__ Wih0, const float* __restrict__ Whh0,
                 const float* __restrict__ bias0,
                 const float* __restrict__ Wih1, const float* __restrict__ Whh1,
                 const float* __restrict__ bias1,
                 float* __restrict__ rnn_out)
{
    extern __shared__ __align__(16) float lsm[];
    float* xs    = lsm;                    // [512][32]
    float* h0s   = lsm + SS * 32;          // [32]
    float* h1s   = h0s + 32;               // [32]
    float* y0s   = h1s + 32;               // [32]
    float* z0s   = y0s + 32;               // [128]
    float* z1s   = z0s + 128;              // [128]
    float* mus   = z1s + 128;              // [32]
    float* rstds = mus + 32;               // [32]

    const int tid = threadIdx.x;
    const int b   = blockIdx.x;

    if (tid < 32) {
        mus[tid]   = (tid < HH) ? g_mu[tid]   : 0.f;
        rstds[tid] = (tid < HH) ? g_rstd[tid] : 0.f;
        h0s[tid] = (tid < HH) ? h0[b * HH + tid]            : 0.f;
        h1s[tid] = (tid < HH) ? h0[BB * HH + b * HH + tid]  : 0.f;
        y0s[tid] = 0.f;
    }
    __syncthreads();

    const float* fb = g_flat + (size_t)b * (SS * HH);
    for (int i = tid; i < SS * 32; i += LSTM_THREADS) {
        int s = i >> 5, k = i & 31;
        xs[i] = (k < HH) ? (fb[s * HH + k] - mus[k]) * rstds[k] : 0.f;
    }

    float wi[32], wh[32];
    float bj = 0.f;
    #pragma unroll
    for (int k = 0; k < 32; k++) { wi[k] = 0.f; wh[k] = 0.f; }
    if (tid < 120) {
        #pragma unroll
        for (int k = 0; k < HH; k++) {
            wi[k] = Wih0[tid * HH + k];
            wh[k] = Whh0[tid * HH + k];
        }
        bj = bias0[tid];
    } else if (tid >= 128 && tid < 248) {
        int j = tid - 128;
        #pragma unroll
        for (int k = 0; k < HH; k++) {
            wi[k] = Wih1[j * HH + k];
            wh[k] = Whh1[j * HH + k];
        }
        bj = bias1[j];
    }

    float creg = 0.f;
    if (tid < HH)                          creg = c0[b * HH + tid];
    else if (tid >= 128 && tid < 128+HH)   creg = c0[BB * HH + b * HH + (tid - 128)];

    __syncthreads();

    for (int t = 0; t <= SS; t++) {
        if (t < SS && tid < 120) {
            z0s[tid] = dot_step(xs + t * 32, h0s, wi, wh, bj);
        } else if (t >= 1 && tid >= 128 && tid < 248) {
            z1s[tid - 128] = dot_step(y0s, h1s, wi, wh, bj);
        }
        __syncthreads();
        if (t < SS && tid < HH) {
            float ig = hsig(z0s[tid]);
            float fg = hsig(z0s[30 + tid]);
            float gg = htanh(z0s[60 + tid]);
            float og = hsig(z0s[90 + tid]);
            creg = fg * creg + ig * gg;
            float hh = og * htanh(creg);
            h0s[tid] = hh;
            y0s[tid] = hh;
        } else if (t >= 1 && tid >= 128 && tid < 128 + HH) {
            int u = tid - 128;
            float ig = hsig(z1s[u]);
            float fg = hsig(z1s[30 + u]);
            float gg = htanh(z1s[60 + u]);
            float og = hsig(z1s[90 + u]);
            creg = fg * creg + ig * gg;
            float hh = og * htanh(creg);
            h1s[u] = hh;
            rnn_out[((size_t)b * SS + (t - 1)) * HH + u] = hh;
        }
        __syncthreads();
    }
}

// ================= output GEMM: fp16 mma m16n8k16, 128x128 tiles ==============
__global__ __launch_bounds__(256)
void out_mma_kernel(const float* __restrict__ rnn, const float* __restrict__ bout,
                    float* __restrict__ dorsal)
{
    __shared__ __align__(16) __half a_s[128][40];   // 10.2 KB
    __shared__ __align__(16) __half b_s[128][40];   // 10.2 KB

    const int tid  = threadIdx.x;
    const int wid  = tid >> 5;
    const int lane = tid & 31;
    const int g    = lane >> 2;
    const int tg   = lane & 3;
    const size_t rb = (size_t)(blockIdx.x >> 2) * 128;
    const int cb    = (blockIdx.x & 3) * 128;

    for (int i = tid; i < 128 * 32; i += 256) {
        int r = i >> 5, k = i & 31;
        float v = (k < HH) ? rnn[(rb + r) * HH + k] : 0.f;
        a_s[r][k] = __float2half_rn(v);
    }
    {
        const uint2* wb = (const uint2*)g_woh;   // 8 uint2 per n
        #pragma unroll
        for (int q = 0; q < 4; q++) {
            int idx = q * 256 + tid;             // 0..1023
            int n = idx >> 3, bf = idx & 7;
            *(uint2*)&b_s[n][bf * 4] = wb[(size_t)(cb + n) * 8 + bf];
        }
    }

    float c[16][4];
    #pragma unroll
    for (int nt = 0; nt < 16; nt++) {
        float bv0 = bout[cb + nt * 8 + tg * 2];
        float bv1 = bout[cb + nt * 8 + tg * 2 + 1];
        c[nt][0] = bv0; c[nt][1] = bv1; c[nt][2] = bv0; c[nt][3] = bv1;
    }
    __syncthreads();

    const int mr = wid * 16;
    #pragma unroll
    for (int ks = 0; ks < 2; ks++) {
        const int k0 = ks * 16;
        uint32_t a0 = *(const uint32_t*)&a_s[mr + g    ][k0 + 2*tg    ];
        uint32_t a1 = *(const uint32_t*)&a_s[mr + g + 8][k0 + 2*tg    ];
        uint32_t a2 = *(const uint32_t*)&a_s[mr + g    ][k0 + 2*tg + 8];
        uint32_t a3 = *(const uint32_t*)&a_s[mr + g + 8][k0 + 2*tg + 8];
        #pragma unroll
        for (int nt = 0; nt < 16; nt++) {
            uint32_t b0 = *(const uint32_t*)&b_s[nt*8 + g][k0 + 2*tg    ];
            uint32_t b1 = *(const uint32_t*)&b_s[nt*8 + g][k0 + 2*tg + 8];
            mma_f16(c[nt][0], c[nt][1], c[nt][2], c[nt][3], a0, a1, a2, a3, b0, b1);
        }
    }

    size_t r0 = rb + wid * 16 + g;
    size_t r1 = r0 + 8;
    #pragma unroll
    for (int nt = 0; nt < 16; nt++) {
        int col = cb + nt * 8 + tg * 2;
        *(float2*)&dorsal[r0 * N_OUT + col] = make_float2(c[nt][0], c[nt][1]);
        *(float2*)&dorsal[r1 * N_OUT + col] = make_float2(c[nt][2], c[nt][3]);
    }
}

// ---------------- launch ----------------
extern "C" void kernel_launch(void* const* d_in, const int* in_sizes, int n_in,
                              void* d_out, int out_size)
{
    const float* x     = (const float*)d_in[0];
    const float* h0    = (const float*)d_in[1];
    const float* c0    = (const float*)d_in[2];
    const float* W1    = (const float*)d_in[3];
    const float* b1    = (const float*)d_in[4];
    const float* Wih0  = (const float*)d_in[5];
    const float* Whh0  = (const float*)d_in[6];
    const float* bias0 = (const float*)d_in[7];
    const float* Wih1  = (const float*)d_in[8];
    const float* Whh1  = (const float*)d_in[9];
    const float* bias1 = (const float*)d_in[10];
    const float* Wout  = (const float*)d_in[11];
    const float* bout  = (const float*)d_in[12];

    float* out    = (float*)d_out;
    float* dorsal = out;
    float* rnn    = out + (size_t)ROWS * N_OUT;

    cudaFuncSetAttribute(lstm_kernel, cudaFuncAttributeMaxDynamicSharedMemorySize,
                         LSTM_SMEM_BYTES);

    prep_w_kernel<<<(32 * N_IN + N_OUT * 32) / 256, 256>>>(W1, Wout);
    fc1_mma_kernel<<<ROWS / 128, 256>>>(x, b1);
    bn_stats_kernel<<<1, 256>>>();
    lstm_kernel<<<BB, LSTM_THREADS, LSTM_SMEM_BYTES>>>(h0, c0, Wih0, Whh0, bias0,
                                                       Wih1, Whh1, bias1, rnn);
    out_mma_kernel<<<(ROWS / 128) * (N_OUT / 128), 256>>>(rnn, bout, dorsal);
}

// round 14
// speedup vs baseline: 1.3218x; 1.3218x over previous
#include <cuda_runtime.h>
#include <cstdint>

#define BB 256
#define SS 512
#define N_IN 2048
#define N_OUT 512
#define HH 30
#define ROWS (BB*SS)   // 131072

// ---------------- device scratch ----------------
__device__ float g_flat[(size_t)ROWS * HH];
__device__ float g_partial[1024 * 64];
__device__ float g_mu[HH];
__device__ float g_rstd[HH];
// pre-converted weights (single rna-tf32), transposed [n][k]
__device__ uint32_t g_w1t[32 * N_IN];      // 256 KB
__device__ uint32_t g_wot[N_OUT * 32];     // 64 KB

// ---------------- helpers ----------------
__device__ __forceinline__ uint32_t cvt_tf32(float f) {
    uint32_t u; asm("cvt.rna.tf32.f32 %0, %1;" : "=r"(u) : "f"(f)); return u;
}
__device__ __forceinline__ float cvt_tf32f(float f) {
    return __uint_as_float(cvt_tf32(f));
}
__device__ __forceinline__ void mma_tf32(float& c0, float& c1, float& c2, float& c3,
                                         uint32_t a0, uint32_t a1, uint32_t a2, uint32_t a3,
                                         uint32_t b0, uint32_t b1) {
    asm volatile(
        "mma.sync.aligned.m16n8k8.row.col.f32.tf32.tf32.f32 "
        "{%0,%1,%2,%3},{%4,%5,%6,%7},{%8,%9},{%0,%1,%2,%3};"
        : "+f"(c0), "+f"(c1), "+f"(c2), "+f"(c3)
        : "r"(a0), "r"(a1), "r"(a2), "r"(a3), "r"(b0), "r"(b1));
}
__device__ __forceinline__ float htanh(float x) {
    float r; asm("tanh.approx.f32 %0,%1;" : "=f"(r) : "f"(x)); return r;
}
__device__ __forceinline__ float hsig(float x) {
    return fmaf(htanh(x * 0.5f), 0.5f, 0.5f);
}

// ---------------- prep: W1/Wout -> tf32 (rna), transposed [n][k] ----------
__global__ __launch_bounds__(256)
void prep_w_kernel(const float* __restrict__ W1, const float* __restrict__ Wout)
{
    int i = blockIdx.x * 256 + threadIdx.x;
    if (i < 32 * N_IN) {
        int k = i >> 5, n = i & 31;
        float w = (n < HH) ? W1[(size_t)k * HH + n] : 0.f;
        g_w1t[n * N_IN + k] = cvt_tf32(w);
    }
    int j = i - 32 * N_IN;
    if (j >= 0 && j < N_OUT * 32) {
        int n = j >> 5, k = j & 31;
        float w = (k < HH) ? Wout[(size_t)k * N_OUT + n] : 0.f;
        g_wot[n * 32 + k] = cvt_tf32(w);
    }
}

// ================= fc1: tf32 mma.sync, double-buffered (R8 exact) ============
#define FC1_A_FL (2*128*36)
#define FC1_B_FL (2*32*36)
#define FC1_SMEM_BYTES ((FC1_A_FL + FC1_B_FL + 32 + 512) * 4)

__global__ __launch_bounds__(256)
void fc1_mma_kernel(const float* __restrict__ x, const float* __restrict__ b1)
{
    extern __shared__ __align__(16) float sm[];
    float* a_s    = sm;                               // [2][128][36]
    float* b_s    = sm + FC1_A_FL;                    // [2][32][36]
    float* bias_s = sm + FC1_A_FL + FC1_B_FL;         // [32]
    float* red    = bias_s + 32;                      // [2][256]

    const int tid  = threadIdx.x;
    const int wid  = tid >> 5;
    const int lane = tid & 31;
    const int g    = lane >> 2;
    const int tg   = lane & 3;
    const size_t rowBase = (size_t)blockIdx.x * 128;

    if (tid < 32) bias_s[tid] = (tid < HH) ? b1[tid] : 0.f;

    float c[4][4];
    #pragma unroll
    for (int nt = 0; nt < 4; nt++)
        #pragma unroll
        for (int q = 0; q < 4; q++) c[nt][q] = 0.f;

    const int ar = tid >> 1;
    const int kb = (tid & 1) * 16;
    const int bn = tid >> 3;
    const int bf = tid & 7;
    float4 pfa4[4];
    float4 pfb;

    auto prefetch = [&](int j) {
        const float* xp = &x[(rowBase + ar) * (size_t)N_IN + j * 32 + kb];
        #pragma unroll
        for (int q = 0; q < 4; q++) pfa4[q] = *(const float4*)(xp + q * 4);
        const float4* wb = (const float4*)g_w1t;
        pfb = wb[(size_t)bn * (N_IN / 4) + j * 8 + bf];
    };
    auto store_stage = [&](int st) {
        float* ap = &a_s[st * 4608 + ar * 36 + kb];
        #pragma unroll
        for (int q = 0; q < 4; q++) {
            ap[q*4+0] = cvt_tf32f(pfa4[q].x);
            ap[q*4+1] = cvt_tf32f(pfa4[q].y);
            ap[q*4+2] = cvt_tf32f(pfa4[q].z);
            ap[q*4+3] = cvt_tf32f(pfa4[q].w);
        }
        *(float4*)&b_s[st * 1152 + bn * 36 + bf * 4] = pfb;
    };

    prefetch(0);
    store_stage(0);
    __syncthreads();
    prefetch(1);

    const int mr = wid * 16;
    for (int j = 0; j < 64; j++) {
        const int cur = j & 1, nxt = cur ^ 1;
        if (j < 63) store_stage(nxt);
        if (j < 62) prefetch(j + 2);
        const float* ab  = &a_s[cur * 4608];
        const float* bbp = &b_s[cur * 1152];
        #pragma unroll
        for (int ks = 0; ks < 4; ks++) {
            const int k0 = ks * 8;
            uint32_t a0 = __float_as_uint(ab[(mr + g    ) * 36 + k0 + tg    ]);
            uint32_t a1 = __float_as_uint(ab[(mr + g + 8) * 36 + k0 + tg    ]);
            uint32_t a2 = __float_as_uint(ab[(mr + g    ) * 36 + k0 + tg + 4]);
            uint32_t a3 = __float_as_uint(ab[(mr + g + 8) * 36 + k0 + tg + 4]);
            #pragma unroll
            for (int nt = 0; nt < 4; nt++) {
                uint32_t b0 = __float_as_uint(bbp[(nt*8 + g) * 36 + k0 + tg    ]);
                uint32_t b1 = __float_as_uint(bbp[(nt*8 + g) * 36 + k0 + tg + 4]);
                mma_tf32(c[nt][0], c[nt][1], c[nt][2], c[nt][3], a0, a1, a2, a3, b0, b1);
            }
        }
        __syncthreads();
    }

    size_t r0 = rowBase + wid * 16 + g;
    size_t r1 = r0 + 8;
    #pragma unroll
    for (int nt = 0; nt < 4; nt++) {
        int col = nt * 8 + tg * 2;
        float v00 = 0.f, v01 = 0.f, v10 = 0.f, v11 = 0.f;
        if (col < HH) {
            v00 = fmaxf(c[nt][0] + bias_s[col],     0.f);
            v01 = fmaxf(c[nt][1] + bias_s[col + 1], 0.f);
            v10 = fmaxf(c[nt][2] + bias_s[col],     0.f);
            v11 = fmaxf(c[nt][3] + bias_s[col + 1], 0.f);
            *(float2*)&g_flat[r0 * HH + col] = make_float2(v00, v01);
            *(float2*)&g_flat[r1 * HH + col] = make_float2(v10, v11);
        }
        float s0 = v00 + v10, q0 = v00 * v00 + v10 * v10;
        float s1 = v01 + v11, q1 = v01 * v01 + v11 * v11;
        #pragma unroll
        for (int off = 4; off < 32; off <<= 1) {
            s0 += __shfl_xor_sync(0xffffffffu, s0, off);
            q0 += __shfl_xor_sync(0xffffffffu, q0, off);
            s1 += __shfl_xor_sync(0xffffffffu, s1, off);
            q1 += __shfl_xor_sync(0xffffffffu, q1, off);
        }
        if (g == 0) {
            red[(col    ) * 8 + wid]       = s0;
            red[(col + 1) * 8 + wid]       = s1;
            red[256 + (col    ) * 8 + wid] = q0;
            red[256 + (col + 1) * 8 + wid] = q1;
        }
    }
    __syncthreads();
    if (tid < HH) {
        float s = 0.f, q = 0.f;
        #pragma unroll
        for (int w = 0; w < 8; w++) { s += red[tid * 8 + w]; q += red[256 + tid * 8 + w]; }
        g_partial[blockIdx.x * 60 + tid]      = s;
        g_partial[blockIdx.x * 60 + 30 + tid] = q;
    }
}

// ---------------- BN finalize ----------------
__global__ void bn_stats_kernel()
{
    __shared__ float rs[2][HH][9];
    int c = threadIdx.x & 31;
    int g = threadIdx.x >> 5;
    if (c < HH) {
        float s = 0.f, q = 0.f;
        for (int p = g; p < 1024; p += 8) {
            s += g_partial[p * 60 + c];
            q += g_partial[p * 60 + 30 + c];
        }
        rs[0][c][g] = s; rs[1][c][g] = q;
    }
    __syncthreads();
    if (threadIdx.x < HH) {
        float s = 0.f, q = 0.f;
        #pragma unroll
        for (int g2 = 0; g2 < 8; g2++) { s += rs[0][threadIdx.x][g2]; q += rs[1][threadIdx.x][g2]; }
        const float n = (float)ROWS;
        float mu  = s / n;
        float var = q / n - mu * mu;
        g_mu[threadIdx.x]   = mu;
        g_rstd[threadIdx.x] = rsqrtf(var + 1e-5f);
    }
}

// ---------------- LSTM: tensor-core recurrence ------------------------------
// Warps 0-3: layer0 gate rows (128 padded), A = [Wih0 | Whh0] in registers as
// m16k8 fragments, B = (x_t ‖ h0) broadcast over n. Warps 4-7: layer1 with
// B = (y0 ‖ h1). Activation lanes identical to the proven R8 structure.
#define LSTM_THREADS 256
#define LSTM_SMEM_FLOATS (SS*32 + 32 + 32 + 32 + 128 + 128 + 32 + 32)
#define LSTM_SMEM_BYTES  (LSTM_SMEM_FLOATS * 4)

__device__ __forceinline__ float wcat(const float* __restrict__ Wih,
                                      const float* __restrict__ Whh,
                                      int row, int k)
{
    if (row >= 120) return 0.f;
    if (k < 32)  return (k < HH)      ? Wih[row * HH + k]        : 0.f;
    return (k - 32 < HH) ? Whh[row * HH + (k - 32)] : 0.f;
}

__global__ __launch_bounds__(LSTM_THREADS, 2)
void lstm_kernel(const float* __restrict__ h0, const float* __restrict__ c0,
                 const float* __restrict__ Wih0, const float* __restrict__ Whh0,
                 const float* __restrict__ bias0,
                 const float* __restrict__ Wih1, const float* __restrict__ Whh1,
                 const float* __restrict__ bias1,
                 float* __restrict__ rnn_out)
{
    extern __shared__ __align__(16) float lsm[];
    float* xs    = lsm;                    // [512][32] tf32-rounded normalized x
    float* h0s   = lsm + SS * 32;          // [32]
    float* h1s   = h0s + 32;               // [32]
    float* y0s   = h1s + 32;               // [32]
    float* z0s   = y0s + 32;               // [128]
    float* z1s   = z0s + 128;              // [128]
    float* mus   = z1s + 128;              // [32]
    float* rstds = mus + 32;               // [32]

    const int tid  = threadIdx.x;
    const int wid  = tid >> 5;
    const int lane = tid & 31;
    const int g    = lane >> 2;
    const int tg   = lane & 3;
    const int b    = blockIdx.x;

    if (tid < 32) {
        mus[tid]   = (tid < HH) ? g_mu[tid]   : 0.f;
        rstds[tid] = (tid < HH) ? g_rstd[tid] : 0.f;
        h0s[tid] = (tid < HH) ? cvt_tf32f(h0[b * HH + tid])           : 0.f;
        h1s[tid] = (tid < HH) ? cvt_tf32f(h0[BB * HH + b * HH + tid]) : 0.f;
        y0s[tid] = 0.f;
    }
    __syncthreads();

    const float* fb = g_flat + (size_t)b * (SS * HH);
    for (int i = tid; i < SS * 32; i += LSTM_THREADS) {
        int s = i >> 5, k = i & 31;
        xs[i] = (k < HH) ? cvt_tf32f((fb[s * HH + k] - mus[k]) * rstds[k]) : 0.f;
    }

    // weight fragments (per-warp tiles; 2 row-tiles of 16, 8 k-steps)
    const float* Wih = (wid < 4) ? Wih0 : Wih1;
    const float* Whh = (wid < 4) ? Whh0 : Whh1;
    const float* bia = (wid < 4) ? bias0 : bias1;
    const int w4 = wid & 3;
    uint32_t af[2][8][4];
    #pragma unroll
    for (int t2 = 0; t2 < 2; t2++) {
        int r0 = w4 * 32 + t2 * 16 + g;
        #pragma unroll
        for (int ks = 0; ks < 8; ks++) {
            af[t2][ks][0] = cvt_tf32(wcat(Wih, Whh, r0,     ks * 8 + tg));
            af[t2][ks][1] = cvt_tf32(wcat(Wih, Whh, r0 + 8, ks * 8 + tg));
            af[t2][ks][2] = cvt_tf32(wcat(Wih, Whh, r0,     ks * 8 + tg + 4));
            af[t2][ks][3] = cvt_tf32(wcat(Wih, Whh, r0 + 8, ks * 8 + tg + 4));
        }
    }
    float bz[4];
    #pragma unroll
    for (int p = 0; p < 4; p++) {
        int r = w4 * 32 + (p >> 1) * 16 + (p & 1) * 8 + g;
        bz[p] = (r < 120) ? bia[r] : 0.f;
    }

    float creg = 0.f;
    if (tid < HH)                          creg = c0[b * HH + tid];
    else if (tid >= 128 && tid < 128+HH)   creg = c0[BB * HH + b * HH + (tid - 128)];

    __syncthreads();

    for (int t = 0; t <= SS; t++) {
        if (wid < 4) {
            if (t < SS) {
                float cc[2][4];
                #pragma unroll
                for (int t2 = 0; t2 < 2; t2++)
                    #pragma unroll
                    for (int q = 0; q < 4; q++) cc[t2][q] = 0.f;
                const float* xb = xs + t * 32;
                #pragma unroll
                for (int ks = 0; ks < 8; ks++) {
                    float bv0, bv1;
                    if (ks < 4) { bv0 = xb[ks * 8 + tg];       bv1 = xb[ks * 8 + tg + 4]; }
                    else        { bv0 = h0s[ks * 8 + tg - 32]; bv1 = h0s[ks * 8 + tg - 28]; }
                    uint32_t ub0 = __float_as_uint(bv0), ub1 = __float_as_uint(bv1);
                    mma_tf32(cc[0][0], cc[0][1], cc[0][2], cc[0][3],
                             af[0][ks][0], af[0][ks][1], af[0][ks][2], af[0][ks][3], ub0, ub1);
                    mma_tf32(cc[1][0], cc[1][1], cc[1][2], cc[1][3],
                             af[1][ks][0], af[1][ks][1], af[1][ks][2], af[1][ks][3], ub0, ub1);
                }
                if (tg == 0) {
                    z0s[w4 * 32 + g]      = cc[0][0] + bz[0];
                    z0s[w4 * 32 + g + 8]  = cc[0][2] + bz[1];
                    z0s[w4 * 32 + g + 16] = cc[1][0] + bz[2];
                    z0s[w4 * 32 + g + 24] = cc[1][2] + bz[3];
                }
            }
        } else {
            if (t >= 1) {
                float cc[2][4];
                #pragma unroll
                for (int t2 = 0; t2 < 2; t2++)
                    #pragma unroll
                    for (int q = 0; q < 4; q++) cc[t2][q] = 0.f;
                #pragma unroll
                for (int ks = 0; ks < 8; ks++) {
                    float bv0, bv1;
                    if (ks < 4) { bv0 = y0s[ks * 8 + tg];      bv1 = y0s[ks * 8 + tg + 4]; }
                    else        { bv0 = h1s[ks * 8 + tg - 32]; bv1 = h1s[ks * 8 + tg - 28]; }
                    uint32_t ub0 = __float_as_uint(bv0), ub1 = __float_as_uint(bv1);
                    mma_tf32(cc[0][0], cc[0][1], cc[0][2], cc[0][3],
                             af[0][ks][0], af[0][ks][1], af[0][ks][2], af[0][ks][3], ub0, ub1);
                    mma_tf32(cc[1][0], cc[1][1], cc[1][2], cc[1][3],
                             af[1][ks][0], af[1][ks][1], af[1][ks][2], af[1][ks][3], ub0, ub1);
                }
                if (tg == 0) {
                    z1s[w4 * 32 + g]      = cc[0][0] + bz[0];
                    z1s[w4 * 32 + g + 8]  = cc[0][2] + bz[1];
                    z1s[w4 * 32 + g + 16] = cc[1][0] + bz[2];
                    z1s[w4 * 32 + g + 24] = cc[1][2] + bz[3];
                }
            }
        }
        __syncthreads();
        if (t < SS && tid < HH) {
            float ig = hsig(z0s[tid]);
            float fg = hsig(z0s[30 + tid]);
            float gg = htanh(z0s[60 + tid]);
            float og = hsig(z0s[90 + tid]);
            creg = fg * creg + ig * gg;
            float hh = og * htanh(creg);
            float hr = cvt_tf32f(hh);
            h0s[tid] = hr;
            y0s[tid] = hr;
        } else if (t >= 1 && tid >= 128 && tid < 128 + HH) {
            int u = tid - 128;
            float ig = hsig(z1s[u]);
            float fg = hsig(z1s[30 + u]);
            float gg = htanh(z1s[60 + u]);
            float og = hsig(z1s[90 + u]);
            creg = fg * creg + ig * gg;
            float hh = og * htanh(creg);
            h1s[u] = cvt_tf32f(hh);
            rnn_out[((size_t)b * SS + (t - 1)) * HH + u] = hh;
        }
        __syncthreads();
    }
}

// ================= output GEMM: tf32 mma.sync, 128x128 tiles (R8 exact) =======
#define OG_A_FL (128*36)
#define OG_B_FL (128*36)
#define OG_SMEM_BYTES ((OG_A_FL + OG_B_FL) * 4)

__global__ __launch_bounds__(256)
void out_mma_kernel(const float* __restrict__ rnn, const float* __restrict__ bout,
                    float* __restrict__ dorsal)
{
    extern __shared__ __align__(16) float sm[];
    float* a_s = sm;
    float* b_s = sm + OG_A_FL;

    const int tid  = threadIdx.x;
    const int wid  = tid >> 5;
    const int lane = tid & 31;
    const int g    = lane >> 2;
    const int tg   = lane & 3;
    const size_t rb = (size_t)(blockIdx.x >> 2) * 128;
    const int cb    = (blockIdx.x & 3) * 128;

    for (int i = tid; i < 128 * 32; i += 256) {
        int r = i >> 5, k = i & 31;
        float v = (k < HH) ? rnn[(rb + r) * HH + k] : 0.f;
        a_s[r * 36 + k] = cvt_tf32f(v);
    }
    {
        const float4* wb = (const float4*)g_wot;
        #pragma unroll
        for (int q = 0; q < 4; q++) {
            int idx = q * 256 + tid;
            int n = idx >> 3, fi = idx & 7;
            float4 v = wb[(size_t)(cb + n) * 8 + fi];
            *(float4*)&b_s[n * 36 + fi * 4] = v;
        }
    }

    float c[16][4];
    #pragma unroll
    for (int nt = 0; nt < 16; nt++) {
        float bv0 = bout[cb + nt * 8 + tg * 2];
        float bv1 = bout[cb + nt * 8 + tg * 2 + 1];
        c[nt][0] = bv0; c[nt][1] = bv1; c[nt][2] = bv0; c[nt][3] = bv1;
    }
    __syncthreads();

    const int mr = wid * 16;
    #pragma unroll
    for (int ks = 0; ks < 4; ks++) {
        const int k0 = ks * 8;
        uint32_t a0 = __float_as_uint(a_s[(mr + g    ) * 36 + k0 + tg    ]);
        uint32_t a1 = __float_as_uint(a_s[(mr + g + 8) * 36 + k0 + tg    ]);
        uint32_t a2 = __float_as_uint(a_s[(mr + g    ) * 36 + k0 + tg + 4]);
        uint32_t a3 = __float_as_uint(a_s[(mr + g + 8) * 36 + k0 + tg + 4]);
        #pragma unroll
        for (int nt = 0; nt < 16; nt++) {
            uint32_t b0 = __float_as_uint(b_s[(nt*8 + g) * 36 + k0 + tg    ]);
            uint32_t b1 = __float_as_uint(b_s[(nt*8 + g) * 36 + k0 + tg + 4]);
            mma_tf32(c[nt][0], c[nt][1], c[nt][2], c[nt][3], a0, a1, a2, a3, b0, b1);
        }
    }

    size_t r0 = rb + wid * 16 + g;
    size_t r1 = r0 + 8;
    #pragma unroll
    for (int nt = 0; nt < 16; nt++) {
        int col = cb + nt * 8 + tg * 2;
        *(float2*)&dorsal[r0 * N_OUT + col] = make_float2(c[nt][0], c[nt][1]);
        *(float2*)&dorsal[r1 * N_OUT + col] = make_float2(c[nt][2], c[nt][3]);
    }
}

// ---------------- launch ----------------
extern "C" void kernel_launch(void* const* d_in, const int* in_sizes, int n_in,
                              void* d_out, int out_size)
{
    const float* x     = (const float*)d_in[0];
    const float* h0    = (const float*)d_in[1];
    const float* c0    = (const float*)d_in[2];
    const float* W1    = (const float*)d_in[3];
    const float* b1    = (const float*)d_in[4];
    const float* Wih0  = (const float*)d_in[5];
    const float* Whh0  = (const float*)d_in[6];
    const float* bias0 = (const float*)d_in[7];
    const float* Wih1  = (const float*)d_in[8];
    const float* Whh1  = (const float*)d_in[9];
    const float* bias1 = (const float*)d_in[10];
    const float* Wout  = (const float*)d_in[11];
    const float* bout  = (const float*)d_in[12];

    float* out    = (float*)d_out;
    float* dorsal = out;
    float* rnn    = out + (size_t)ROWS * N_OUT;

    cudaFuncSetAttribute(fc1_mma_kernel, cudaFuncAttributeMaxDynamicSharedMemorySize,
                         FC1_SMEM_BYTES);
    cudaFuncSetAttribute(out_mma_kernel, cudaFuncAttributeMaxDynamicSharedMemorySize,
                         OG_SMEM_BYTES);
    cudaFuncSetAttribute(lstm_kernel, cudaFuncAttributeMaxDynamicSharedMemorySize,
                         LSTM_SMEM_BYTES);

    prep_w_kernel<<<(32 * N_IN + N_OUT * 32) / 256, 256>>>(W1, Wout);
    fc1_mma_kernel<<<ROWS / 128, 256, FC1_SMEM_BYTES>>>(x, b1);
    bn_stats_kernel<<<1, 256>>>();
    lstm_kernel<<<BB, LSTM_THREADS, LSTM_SMEM_BYTES>>>(h0, c0, Wih0, Whh0, bias0,
                                                       Wih1, Whh1, bias1, rnn);
    out_mma_kernel<<<(ROWS / 128) * (N_OUT / 128), 256, OG_SMEM_BYTES>>>(rnn, bout, dorsal);
}

// round 15
// speedup vs baseline: 1.3249x; 1.0023x over previous
#include <cuda_runtime.h>
#include <cstdint>

#define BB 256
#define SS 512
#define N_IN 2048
#define N_OUT 512
#define HH 30
#define ROWS (BB*SS)   // 131072

// ---------------- device scratch ----------------
__device__ float g_flat[(size_t)ROWS * HH];
__device__ float g_partial[1024 * 64];
__device__ float g_mu[HH];
__device__ float g_rstd[HH];
// pre-converted weights (single rna-tf32), transposed [n][k]
__device__ uint32_t g_w1t[32 * N_IN];      // 256 KB
__device__ uint32_t g_wot[N_OUT * 32];     // 64 KB

// ---------------- helpers ----------------
__device__ __forceinline__ uint32_t cvt_tf32(float f) {
    uint32_t u; asm("cvt.rna.tf32.f32 %0, %1;" : "=r"(u) : "f"(f)); return u;
}
__device__ __forceinline__ float cvt_tf32f(float f) {
    return __uint_as_float(cvt_tf32(f));
}
__device__ __forceinline__ void mma_tf32(float& c0, float& c1, float& c2, float& c3,
                                         uint32_t a0, uint32_t a1, uint32_t a2, uint32_t a3,
                                         uint32_t b0, uint32_t b1) {
    asm volatile(
        "mma.sync.aligned.m16n8k8.row.col.f32.tf32.tf32.f32 "
        "{%0,%1,%2,%3},{%4,%5,%6,%7},{%8,%9},{%0,%1,%2,%3};"
        : "+f"(c0), "+f"(c1), "+f"(c2), "+f"(c3)
        : "r"(a0), "r"(a1), "r"(a2), "r"(a3), "r"(b0), "r"(b1));
}
__device__ __forceinline__ float htanh(float x) {
    float r; asm("tanh.approx.f32 %0,%1;" : "=f"(r) : "f"(x)); return r;
}
__device__ __forceinline__ float hsig(float x) {
    return fmaf(htanh(x * 0.5f), 0.5f, 0.5f);
}

// ---------------- prep: W1/Wout -> tf32 (rna), transposed [n][k] ----------
__global__ __launch_bounds__(256)
void prep_w_kernel(const float* __restrict__ W1, const float* __restrict__ Wout)
{
    int i = blockIdx.x * 256 + threadIdx.x;
    if (i < 32 * N_IN) {
        int k = i >> 5, n = i & 31;
        float w = (n < HH) ? W1[(size_t)k * HH + n] : 0.f;
        g_w1t[n * N_IN + k] = cvt_tf32(w);
    }
    int j = i - 32 * N_IN;
    if (j >= 0 && j < N_OUT * 32) {
        int n = j >> 5, k = j & 31;
        float w = (k < HH) ? Wout[(size_t)k * N_OUT + n] : 0.f;
        g_wot[n * 32 + k] = cvt_tf32(w);
    }
}

// ================= fc1: tf32 mma.sync, double-buffered (R8 exact) ============
#define FC1_A_FL (2*128*36)
#define FC1_B_FL (2*32*36)
#define FC1_SMEM_BYTES ((FC1_A_FL + FC1_B_FL + 32 + 512) * 4)

__global__ __launch_bounds__(256)
void fc1_mma_kernel(const float* __restrict__ x, const float* __restrict__ b1)
{
    extern __shared__ __align__(16) float sm[];
    float* a_s    = sm;                               // [2][128][36]
    float* b_s    = sm + FC1_A_FL;                    // [2][32][36]
    float* bias_s = sm + FC1_A_FL + FC1_B_FL;         // [32]
    float* red    = bias_s + 32;                      // [2][256]

    const int tid  = threadIdx.x;
    const int wid  = tid >> 5;
    const int lane = tid & 31;
    const int g    = lane >> 2;
    const int tg   = lane & 3;
    const size_t rowBase = (size_t)blockIdx.x * 128;

    if (tid < 32) bias_s[tid] = (tid < HH) ? b1[tid] : 0.f;

    float c[4][4];
    #pragma unroll
    for (int nt = 0; nt < 4; nt++)
        #pragma unroll
        for (int q = 0; q < 4; q++) c[nt][q] = 0.f;

    const int ar = tid >> 1;
    const int kb = (tid & 1) * 16;
    const int bn = tid >> 3;
    const int bf = tid & 7;
    float4 pfa4[4];
    float4 pfb;

    auto prefetch = [&](int j) {
        const float* xp = &x[(rowBase + ar) * (size_t)N_IN + j * 32 + kb];
        #pragma unroll
        for (int q = 0; q < 4; q++) pfa4[q] = *(const float4*)(xp + q * 4);
        const float4* wb = (const float4*)g_w1t;
        pfb = wb[(size_t)bn * (N_IN / 4) + j * 8 + bf];
    };
    auto store_stage = [&](int st) {
        float* ap = &a_s[st * 4608 + ar * 36 + kb];
        #pragma unroll
        for (int q = 0; q < 4; q++) {
            ap[q*4+0] = cvt_tf32f(pfa4[q].x);
            ap[q*4+1] = cvt_tf32f(pfa4[q].y);
            ap[q*4+2] = cvt_tf32f(pfa4[q].z);
            ap[q*4+3] = cvt_tf32f(pfa4[q].w);
        }
        *(float4*)&b_s[st * 1152 + bn * 36 + bf * 4] = pfb;
    };

    prefetch(0);
    store_stage(0);
    __syncthreads();
    prefetch(1);

    const int mr = wid * 16;
    for (int j = 0; j < 64; j++) {
        const int cur = j & 1, nxt = cur ^ 1;
        if (j < 63) store_stage(nxt);
        if (j < 62) prefetch(j + 2);
        const float* ab  = &a_s[cur * 4608];
        const float* bbp = &b_s[cur * 1152];
        #pragma unroll
        for (int ks = 0; ks < 4; ks++) {
            const int k0 = ks * 8;
            uint32_t a0 = __float_as_uint(ab[(mr + g    ) * 36 + k0 + tg    ]);
            uint32_t a1 = __float_as_uint(ab[(mr + g + 8) * 36 + k0 + tg    ]);
            uint32_t a2 = __float_as_uint(ab[(mr + g    ) * 36 + k0 + tg + 4]);
            uint32_t a3 = __float_as_uint(ab[(mr + g + 8) * 36 + k0 + tg + 4]);
            #pragma unroll
            for (int nt = 0; nt < 4; nt++) {
                uint32_t b0 = __float_as_uint(bbp[(nt*8 + g) * 36 + k0 + tg    ]);
                uint32_t b1 = __float_as_uint(bbp[(nt*8 + g) * 36 + k0 + tg + 4]);
                mma_tf32(c[nt][0], c[nt][1], c[nt][2], c[nt][3], a0, a1, a2, a3, b0, b1);
            }
        }
        __syncthreads();
    }

    size_t r0 = rowBase + wid * 16 + g;
    size_t r1 = r0 + 8;
    #pragma unroll
    for (int nt = 0; nt < 4; nt++) {
        int col = nt * 8 + tg * 2;
        float v00 = 0.f, v01 = 0.f, v10 = 0.f, v11 = 0.f;
        if (col < HH) {
            v00 = fmaxf(c[nt][0] + bias_s[col],     0.f);
            v01 = fmaxf(c[nt][1] + bias_s[col + 1], 0.f);
            v10 = fmaxf(c[nt][2] + bias_s[col],     0.f);
            v11 = fmaxf(c[nt][3] + bias_s[col + 1], 0.f);
            *(float2*)&g_flat[r0 * HH + col] = make_float2(v00, v01);
            *(float2*)&g_flat[r1 * HH + col] = make_float2(v10, v11);
        }
        float s0 = v00 + v10, q0 = v00 * v00 + v10 * v10;
        float s1 = v01 + v11, q1 = v01 * v01 + v11 * v11;
        #pragma unroll
        for (int off = 4; off < 32; off <<= 1) {
            s0 += __shfl_xor_sync(0xffffffffu, s0, off);
            q0 += __shfl_xor_sync(0xffffffffu, q0, off);
            s1 += __shfl_xor_sync(0xffffffffu, s1, off);
            q1 += __shfl_xor_sync(0xffffffffu, q1, off);
        }
        if (g == 0) {
            red[(col    ) * 8 + wid]       = s0;
            red[(col + 1) * 8 + wid]       = s1;
            red[256 + (col    ) * 8 + wid] = q0;
            red[256 + (col + 1) * 8 + wid] = q1;
        }
    }
    __syncthreads();
    if (tid < HH) {
        float s = 0.f, q = 0.f;
        #pragma unroll
        for (int w = 0; w < 8; w++) { s += red[tid * 8 + w]; q += red[256 + tid * 8 + w]; }
        g_partial[blockIdx.x * 60 + tid]      = s;
        g_partial[blockIdx.x * 60 + 30 + tid] = q;
    }
}

// ---------------- BN finalize ----------------
__global__ void bn_stats_kernel()
{
    __shared__ float rs[2][HH][9];
    int c = threadIdx.x & 31;
    int g = threadIdx.x >> 5;
    if (c < HH) {
        float s = 0.f, q = 0.f;
        for (int p = g; p < 1024; p += 8) {
            s += g_partial[p * 60 + c];
            q += g_partial[p * 60 + 30 + c];
        }
        rs[0][c][g] = s; rs[1][c][g] = q;
    }
    __syncthreads();
    if (threadIdx.x < HH) {
        float s = 0.f, q = 0.f;
        #pragma unroll
        for (int g2 = 0; g2 < 8; g2++) { s += rs[0][threadIdx.x][g2]; q += rs[1][threadIdx.x][g2]; }
        const float n = (float)ROWS;
        float mu  = s / n;
        float var = q / n - mu * mu;
        g_mu[threadIdx.x]   = mu;
        g_rstd[threadIdx.x] = rsqrtf(var + 1e-5f);
    }
}

// ---------------- LSTM: tensor-core recurrence ------------------------------
// Warps 0-3: layer0 gate rows (128 padded), A = [Wih0 | Whh0] in registers as
// m16k8 fragments, B = (x_t ‖ h0) broadcast over n. Warps 4-7: layer1 with
// B = (y0 ‖ h1). Activation lanes identical to the proven R8 structure.
#define LSTM_THREADS 256
#define LSTM_SMEM_FLOATS (SS*32 + 32 + 32 + 32 + 128 + 128 + 32 + 32)
#define LSTM_SMEM_BYTES  (LSTM_SMEM_FLOATS * 4)

__device__ __forceinline__ float wcat(const float* __restrict__ Wih,
                                      const float* __restrict__ Whh,
                                      int row, int k)
{
    if (row >= 120) return 0.f;
    if (k < 32)  return (k < HH)      ? Wih[row * HH + k]        : 0.f;
    return (k - 32 < HH) ? Whh[row * HH + (k - 32)] : 0.f;
}

__global__ __launch_bounds__(LSTM_THREADS, 2)
void lstm_kernel(const float* __restrict__ h0, const float* __restrict__ c0,
                 const float* __restrict__ Wih0, const float* __restrict__ Whh0,
                 const float* __restrict__ bias0,
                 const float* __restrict__ Wih1, const float* __restrict__ Whh1,
                 const float* __restrict__ bias1,
                 float* __restrict__ rnn_out)
{
    extern __shared__ __align__(16) float lsm[];
    float* xs    = lsm;                    // [512][32] tf32-rounded normalized x
    float* h0s   = lsm + SS * 32;          // [32]
    float* h1s   = h0s + 32;               // [32]
    float* y0s   = h1s + 32;               // [32]
    float* z0s   = y0s + 32;               // [128]
    float* z1s   = z0s + 128;              // [128]
    float* mus   = z1s + 128;              // [32]
    float* rstds = mus + 32;               // [32]

    const int tid  = threadIdx.x;
    const int wid  = tid >> 5;
    const int lane = tid & 31;
    const int g    = lane >> 2;
    const int tg   = lane & 3;
    const int b    = blockIdx.x;

    if (tid < 32) {
        mus[tid]   = (tid < HH) ? g_mu[tid]   : 0.f;
        rstds[tid] = (tid < HH) ? g_rstd[tid] : 0.f;
        h0s[tid] = (tid < HH) ? cvt_tf32f(h0[b * HH + tid])           : 0.f;
        h1s[tid] = (tid < HH) ? cvt_tf32f(h0[BB * HH + b * HH + tid]) : 0.f;
        y0s[tid] = 0.f;
    }
    __syncthreads();

    const float* fb = g_flat + (size_t)b * (SS * HH);
    for (int i = tid; i < SS * 32; i += LSTM_THREADS) {
        int s = i >> 5, k = i & 31;
        xs[i] = (k < HH) ? cvt_tf32f((fb[s * HH + k] - mus[k]) * rstds[k]) : 0.f;
    }

    // weight fragments (per-warp tiles; 2 row-tiles of 16, 8 k-steps)
    const float* Wih = (wid < 4) ? Wih0 : Wih1;
    const float* Whh = (wid < 4) ? Whh0 : Whh1;
    const float* bia = (wid < 4) ? bias0 : bias1;
    const int w4 = wid & 3;
    uint32_t af[2][8][4];
    #pragma unroll
    for (int t2 = 0; t2 < 2; t2++) {
        int r0 = w4 * 32 + t2 * 16 + g;
        #pragma unroll
        for (int ks = 0; ks < 8; ks++) {
            af[t2][ks][0] = cvt_tf32(wcat(Wih, Whh, r0,     ks * 8 + tg));
            af[t2][ks][1] = cvt_tf32(wcat(Wih, Whh, r0 + 8, ks * 8 + tg));
            af[t2][ks][2] = cvt_tf32(wcat(Wih, Whh, r0,     ks * 8 + tg + 4));
            af[t2][ks][3] = cvt_tf32(wcat(Wih, Whh, r0 + 8, ks * 8 + tg + 4));
        }
    }
    float bz[4];
    #pragma unroll
    for (int p = 0; p < 4; p++) {
        int r = w4 * 32 + (p >> 1) * 16 + (p & 1) * 8 + g;
        bz[p] = (r < 120) ? bia[r] : 0.f;
    }

    float creg = 0.f;
    if (tid < HH)                          creg = c0[b * HH + tid];
    else if (tid >= 128 && tid < 128+HH)   creg = c0[BB * HH + b * HH + (tid - 128)];

    __syncthreads();

    for (int t = 0; t <= SS; t++) {
        if (wid < 4) {
            if (t < SS) {
                float cc[2][4];
                #pragma unroll
                for (int t2 = 0; t2 < 2; t2++)
                    #pragma unroll
                    for (int q = 0; q < 4; q++) cc[t2][q] = 0.f;
                const float* xb = xs + t * 32;
                #pragma unroll
                for (int ks = 0; ks < 8; ks++) {
                    float bv0, bv1;
                    if (ks < 4) { bv0 = xb[ks * 8 + tg];       bv1 = xb[ks * 8 + tg + 4]; }
                    else        { bv0 = h0s[ks * 8 + tg - 32]; bv1 = h0s[ks * 8 + tg - 28]; }
                    uint32_t ub0 = __float_as_uint(bv0), ub1 = __float_as_uint(bv1);
                    mma_tf32(cc[0][0], cc[0][1], cc[0][2], cc[0][3],
                             af[0][ks][0], af[0][ks][1], af[0][ks][2], af[0][ks][3], ub0, ub1);
                    mma_tf32(cc[1][0], cc[1][1], cc[1][2], cc[1][3],
                             af[1][ks][0], af[1][ks][1], af[1][ks][2], af[1][ks][3], ub0, ub1);
                }
                if (tg == 0) {
                    z0s[w4 * 32 + g]      = cc[0][0] + bz[0];
                    z0s[w4 * 32 + g + 8]  = cc[0][2] + bz[1];
                    z0s[w4 * 32 + g + 16] = cc[1][0] + bz[2];
                    z0s[w4 * 32 + g + 24] = cc[1][2] + bz[3];
                }
            }
        } else {
            if (t >= 1) {
                float cc[2][4];
                #pragma unroll
                for (int t2 = 0; t2 < 2; t2++)
                    #pragma unroll
                    for (int q = 0; q < 4; q++) cc[t2][q] = 0.f;
                #pragma unroll
                for (int ks = 0; ks < 8; ks++) {
                    float bv0, bv1;
                    if (ks < 4) { bv0 = y0s[ks * 8 + tg];      bv1 = y0s[ks * 8 + tg + 4]; }
                    else        { bv0 = h1s[ks * 8 + tg - 32]; bv1 = h1s[ks * 8 + tg - 28]; }
                    uint32_t ub0 = __float_as_uint(bv0), ub1 = __float_as_uint(bv1);
                    mma_tf32(cc[0][0], cc[0][1], cc[0][2], cc[0][3],
                             af[0][ks][0], af[0][ks][1], af[0][ks][2], af[0][ks][3], ub0, ub1);
                    mma_tf32(cc[1][0], cc[1][1], cc[1][2], cc[1][3],
                             af[1][ks][0], af[1][ks][1], af[1][ks][2], af[1][ks][3], ub0, ub1);
                }
                if (tg == 0) {
                    z1s[w4 * 32 + g]      = cc[0][0] + bz[0];
                    z1s[w4 * 32 + g + 8]  = cc[0][2] + bz[1];
                    z1s[w4 * 32 + g + 16] = cc[1][0] + bz[2];
                    z1s[w4 * 32 + g + 24] = cc[1][2] + bz[3];
                }
            }
        }
        __syncthreads();
        if (t < SS && tid < HH) {
            float ig = hsig(z0s[tid]);
            float fg = hsig(z0s[30 + tid]);
            float gg = htanh(z0s[60 + tid]);
            float og = hsig(z0s[90 + tid]);
            creg = fg * creg + ig * gg;
            float hh = og * htanh(creg);
            float hr = cvt_tf32f(hh);
            h0s[tid] = hr;
            y0s[tid] = hr;
        } else if (t >= 1 && tid >= 128 && tid < 128 + HH) {
            int u = tid - 128;
            float ig = hsig(z1s[u]);
            float fg = hsig(z1s[30 + u]);
            float gg = htanh(z1s[60 + u]);
            float og = hsig(z1s[90 + u]);
            creg = fg * creg + ig * gg;
            float hh = og * htanh(creg);
            h1s[u] = cvt_tf32f(hh);
            rnn_out[((size_t)b * SS + (t - 1)) * HH + u] = hh;
        }
        __syncthreads();
    }
}

// ================= output GEMM: tf32 mma.sync, 128x128 tiles (R8 exact) =======
#define OG_A_FL (128*36)
#define OG_B_FL (128*36)
#define OG_SMEM_BYTES ((OG_A_FL + OG_B_FL) * 4)

__global__ __launch_bounds__(256)
void out_mma_kernel(const float* __restrict__ rnn, const float* __restrict__ bout,
                    float* __restrict__ dorsal)
{
    extern __shared__ __align__(16) float sm[];
    float* a_s = sm;
    float* b_s = sm + OG_A_FL;

    const int tid  = threadIdx.x;
    const int wid  = tid >> 5;
    const int lane = tid & 31;
    const int g    = lane >> 2;
    const int tg   = lane & 3;
    const size_t rb = (size_t)(blockIdx.x >> 2) * 128;
    const int cb    = (blockIdx.x & 3) * 128;

    for (int i = tid; i < 128 * 32; i += 256) {
        int r = i >> 5, k = i & 31;
        float v = (k < HH) ? rnn[(rb + r) * HH + k] : 0.f;
        a_s[r * 36 + k] = cvt_tf32f(v);
    }
    {
        const float4* wb = (const float4*)g_wot;
        #pragma unroll
        for (int q = 0; q < 4; q++) {
            int idx = q * 256 + tid;
            int n = idx >> 3, fi = idx & 7;
            float4 v = wb[(size_t)(cb + n) * 8 + fi];
            *(float4*)&b_s[n * 36 + fi * 4] = v;
        }
    }

    float c[16][4];
    #pragma unroll
    for (int nt = 0; nt < 16; nt++) {
        float bv0 = bout[cb + nt * 8 + tg * 2];
        float bv1 = bout[cb + nt * 8 + tg * 2 + 1];
        c[nt][0] = bv0; c[nt][1] = bv1; c[nt][2] = bv0; c[nt][3] = bv1;
    }
    __syncthreads();

    const int mr = wid * 16;
    #pragma unroll
    for (int ks = 0; ks < 4; ks++) {
        const int k0 = ks * 8;
        uint32_t a0 = __float_as_uint(a_s[(mr + g    ) * 36 + k0 + tg    ]);
        uint32_t a1 = __float_as_uint(a_s[(mr + g + 8) * 36 + k0 + tg    ]);
        uint32_t a2 = __float_as_uint(a_s[(mr + g    ) * 36 + k0 + tg + 4]);
        uint32_t a3 = __float_as_uint(a_s[(mr + g + 8) * 36 + k0 + tg + 4]);
        #pragma unroll
        for (int nt = 0; nt < 16; nt++) {
            uint32_t b0 = __float_as_uint(b_s[(nt*8 + g) * 36 + k0 + tg    ]);
            uint32_t b1 = __float_as_uint(b_s[(nt*8 + g) * 36 + k0 + tg + 4]);
            mma_tf32(c[nt][0], c[nt][1], c[nt][2], c[nt][3], a0, a1, a2, a3, b0, b1);
        }
    }

    size_t r0 = rb + wid * 16 + g;
    size_t r1 = r0 + 8;
    #pragma unroll
    for (int nt = 0; nt < 16; nt++) {
        int col = cb + nt * 8 + tg * 2;
        *(float2*)&dorsal[r0 * N_OUT + col] = make_float2(c[nt][0], c[nt][1]);
        *(float2*)&dorsal[r1 * N_OUT + col] = make_float2(c[nt][2], c[nt][3]);
    }
}

// ---------------- launch ----------------
extern "C" void kernel_launch(void* const* d_in, const int* in_sizes, int n_in,
                              void* d_out, int out_size)
{
    const float* x     = (const float*)d_in[0];
    const float* h0    = (const float*)d_in[1];
    const float* c0    = (const float*)d_in[2];
    const float* W1    = (const float*)d_in[3];
    const float* b1    = (const float*)d_in[4];
    const float* Wih0  = (const float*)d_in[5];
    const float* Whh0  = (const float*)d_in[6];
    const float* bias0 = (const float*)d_in[7];
    const float* Wih1  = (const float*)d_in[8];
    const float* Whh1  = (const float*)d_in[9];
    const float* bias1 = (const float*)d_in[10];
    const float* Wout  = (const float*)d_in[11];
    const float* bout  = (const float*)d_in[12];

    float* out    = (float*)d_out;
    float* dorsal = out;
    float* rnn    = out + (size_t)ROWS * N_OUT;

    cudaFuncSetAttribute(fc1_mma_kernel, cudaFuncAttributeMaxDynamicSharedMemorySize,
                         FC1_SMEM_BYTES);
    cudaFuncSetAttribute(out_mma_kernel, cudaFuncAttributeMaxDynamicSharedMemorySize,
                         OG_SMEM_BYTES);
    cudaFuncSetAttribute(lstm_kernel, cudaFuncAttributeMaxDynamicSharedMemorySize,
                         LSTM_SMEM_BYTES);

    prep_w_kernel<<<(32 * N_IN + N_OUT * 32) / 256, 256>>>(W1, Wout);
    fc1_mma_kernel<<<ROWS / 128, 256, FC1_SMEM_BYTES>>>(x, b1);
    bn_stats_kernel<<<1, 256>>>();
    lstm_kernel<<<BB, LSTM_THREADS, LSTM_SMEM_BYTES>>>(h0, c0, Wih0, Whh0, bias0,
                                                       Wih1, Whh1, bias1, rnn);
    out_mma_kernel<<<(ROWS / 128) * (N_OUT / 128), 256, OG_SMEM_BYTES>>>(rnn, bout, dorsal);
}